// round 1
// baseline (speedup 1.0000x reference)
#include <cuda_runtime.h>
#include <math.h>

// Problem constants
#define B_SZ 4
#define T_SZ 2048
#define C_SZ 1024
#define NH   16
#define HD   64
#define MTOK (B_SZ * T_SZ)          // 8192 tokens
#define QKV_STRIDE (3 * C_SZ)       // 3072

// Scratch (device globals — no allocations allowed)
__device__ float g_qkv[(size_t)MTOK * QKV_STRIDE];  // 96 MB
__device__ float g_y[(size_t)MTOK * C_SZ];          // 32 MB

// ---------------------------------------------------------------------------
// Tiled fp32 GEMM with bias: C[M,N] = A[M,K] @ B[K,N] + bias[N]
// BM=BN=64, BK=16, 256 threads, 4x4 micro-tile per thread.
// Requires M%64==0, N%64==0, K%16==0 (true for all uses here).
// ---------------------------------------------------------------------------
__global__ __launch_bounds__(256) void gemm_bias_kernel(
    const float* __restrict__ A, const float* __restrict__ Bm,
    const float* __restrict__ bias, float* __restrict__ C,
    int M, int N, int K)
{
    __shared__ float As[64][20];  // row stride 20 floats (80B) keeps float4 stores aligned
    __shared__ float Bs[16][64];

    const int tid = threadIdx.x;
    const int tx = tid & 15;      // 0..15 -> output cols 4*tx..4*tx+3
    const int ty = tid >> 4;      // 0..15 -> output rows 4*ty..4*ty+3
    const int bm = blockIdx.y * 64;
    const int bn = blockIdx.x * 64;

    float acc[4][4] = {};

    // per-thread load coordinates (one float4 each per k-tile)
    const int la_r = (tid * 4) >> 4;   // 0..63
    const int la_c = (tid * 4) & 15;   // 0,4,8,12
    const int lb_r = (tid * 4) >> 6;   // 0..15
    const int lb_c = (tid * 4) & 63;   // 0..60

    for (int k0 = 0; k0 < K; k0 += 16) {
        float4 a4 = *(const float4*)(A + (size_t)(bm + la_r) * K + k0 + la_c);
        *(float4*)&As[la_r][la_c] = a4;
        float4 b4 = *(const float4*)(Bm + (size_t)(k0 + lb_r) * N + bn + lb_c);
        *(float4*)&Bs[lb_r][lb_c] = b4;
        __syncthreads();

        #pragma unroll
        for (int kk = 0; kk < 16; kk++) {
            float a[4];
            #pragma unroll
            for (int r = 0; r < 4; r++) a[r] = As[4 * ty + r][kk];
            float4 bq = *(float4*)&Bs[kk][4 * tx];
            float bv[4] = {bq.x, bq.y, bq.z, bq.w};
            #pragma unroll
            for (int r = 0; r < 4; r++)
                #pragma unroll
                for (int c = 0; c < 4; c++)
                    acc[r][c] += a[r] * bv[c];
        }
        __syncthreads();
    }

    // epilogue: add bias, store
    const int col = bn + 4 * tx;
    float4 bb = *(const float4*)(bias + col);
    #pragma unroll
    for (int r = 0; r < 4; r++) {
        const int row = bm + 4 * ty + r;
        float4 o;
        o.x = acc[r][0] + bb.x;
        o.y = acc[r][1] + bb.y;
        o.z = acc[r][2] + bb.z;
        o.w = acc[r][3] + bb.w;
        *(float4*)(C + (size_t)row * N + col) = o;
    }
}

// ---------------------------------------------------------------------------
// RoPE applied in-place to q and k inside the packed qkv buffer.
// One thread per (token, head, rotation pair). Angles up to 2047 -> use
// accurate sincosf/powf (fast intrinsics lose precision at large args).
// ---------------------------------------------------------------------------
__global__ __launch_bounds__(256) void rope_kernel(float* __restrict__ qkv)
{
    int idx = blockIdx.x * blockDim.x + threadIdx.x;  // MTOK*NH*32 total
    int pair = idx & 31;
    int h    = (idx >> 5) & (NH - 1);
    int tok  = idx >> 9;                 // 0..MTOK-1
    int t    = tok & (T_SZ - 1);         // position within sequence

    float invf = powf(10000.0f, -(float)pair / 32.0f);
    float ang = (float)t * invf;
    float s, c;
    sincosf(ang, &s, &c);

    size_t base = (size_t)tok * QKV_STRIDE + h * HD;
    float* q = qkv + base;
    float* k = qkv + base + C_SZ;

    float q1 = q[pair], q2 = q[pair + 32];
    q[pair]      = q1 * c - q2 * s;
    q[pair + 32] = q2 * c + q1 * s;
    float k1 = k[pair], k2 = k[pair + 32];
    k[pair]      = k1 * c - k2 * s;
    k[pair + 32] = k2 * c + k1 * s;
}

// ---------------------------------------------------------------------------
// Flash attention (fp32, causal). One block per (q-tile of 64 rows, head,
// batch). Online softmax. K and V time-share one smem tile.
// Dynamic smem layout (floats):
//   Qs  [64][64]  (pre-scaled by 1/sqrt(d))
//   KVs [64][65]
//   Ss  [64][65]
//   m_s[64], l_s[64], al_s[64]
// ---------------------------------------------------------------------------
#define SM_QS   0
#define SM_KVS  (64 * 64)
#define SM_SS   (SM_KVS + 64 * 65)
#define SM_M    (SM_SS + 64 * 65)
#define SM_L    (SM_M + 64)
#define SM_AL   (SM_L + 64)
#define SMEM_ATTN_FLOATS (SM_AL + 64)
#define SMEM_ATTN_BYTES  (SMEM_ATTN_FLOATS * 4)

__global__ __launch_bounds__(256) void flash_attn_kernel(
    const float* __restrict__ qkv, float* __restrict__ y)
{
    extern __shared__ float sm[];
    float* Qs  = sm + SM_QS;
    float* KVs = sm + SM_KVS;
    float* Ss  = sm + SM_SS;
    float* m_s = sm + SM_M;
    float* l_s = sm + SM_L;
    float* al_s = sm + SM_AL;

    const int qt = blockIdx.x;          // 0..31
    const int h  = blockIdx.y;
    const int b  = blockIdx.z;
    const int tid = threadIdx.x;
    const int tx = tid & 15;
    const int ty = tid >> 4;

    const float* qbase = qkv + (size_t)b * T_SZ * QKV_STRIDE + h * HD;
    const float* kbase = qbase + C_SZ;
    const float* vbase = qbase + 2 * C_SZ;

    // load Q tile (64x64), pre-scale by 1/sqrt(64)=0.125
    {
        int l = tid * 4;                 // one float4 per thread per pass (4096/1024)
        #pragma unroll
        for (int it = 0; it < 4; it++, l += 1024) {
            int r = l >> 6, c = l & 63;
            float4 v = *(const float4*)(qbase + (size_t)(qt * 64 + r) * QKV_STRIDE + c);
            Qs[r * 64 + c + 0] = v.x * 0.125f;
            Qs[r * 64 + c + 1] = v.y * 0.125f;
            Qs[r * 64 + c + 2] = v.z * 0.125f;
            Qs[r * 64 + c + 3] = v.w * 0.125f;
        }
    }
    if (tid < 64) { m_s[tid] = -INFINITY; l_s[tid] = 0.0f; }
    float acc[4][4] = {};
    __syncthreads();

    for (int kt = 0; kt <= qt; kt++) {
        // load K tile into KVs
        {
            int l = tid * 4;
            #pragma unroll
            for (int it = 0; it < 4; it++, l += 1024) {
                int r = l >> 6, c = l & 63;
                float4 v = *(const float4*)(kbase + (size_t)(kt * 64 + r) * QKV_STRIDE + c);
                KVs[r * 65 + c + 0] = v.x;
                KVs[r * 65 + c + 1] = v.y;
                KVs[r * 65 + c + 2] = v.z;
                KVs[r * 65 + c + 3] = v.w;
            }
        }
        __syncthreads();

        // S = Q @ K^T (per thread 4x4)
        float s[4][4] = {};
        #pragma unroll 8
        for (int d = 0; d < 64; d++) {
            float a[4], kv[4];
            #pragma unroll
            for (int r = 0; r < 4; r++) a[r] = Qs[(4 * ty + r) * 64 + d];
            #pragma unroll
            for (int c = 0; c < 4; c++) kv[c] = KVs[(4 * tx + c) * 65 + d];
            #pragma unroll
            for (int r = 0; r < 4; r++)
                #pragma unroll
                for (int c = 0; c < 4; c++)
                    s[r][c] += a[r] * kv[c];
        }
        // write S with causal mask (only diagonal tile can violate)
        const bool diag = (kt == qt);
        #pragma unroll
        for (int r = 0; r < 4; r++) {
            int qi = qt * 64 + 4 * ty + r;
            #pragma unroll
            for (int c = 0; c < 4; c++) {
                int kj = kt * 64 + 4 * tx + c;
                float v = s[r][c];
                if (diag && kj > qi) v = -INFINITY;
                Ss[(4 * ty + r) * 65 + 4 * tx + c] = v;
            }
        }
        __syncthreads();

        // overlap: all threads load V into KVs (K reads are done);
        // threads 0..63 also do the online-softmax row update on Ss.
        {
            int l = tid * 4;
            #pragma unroll
            for (int it = 0; it < 4; it++, l += 1024) {
                int r = l >> 6, c = l & 63;
                float4 v = *(const float4*)(vbase + (size_t)(kt * 64 + r) * QKV_STRIDE + c);
                KVs[r * 65 + c + 0] = v.x;
                KVs[r * 65 + c + 1] = v.y;
                KVs[r * 65 + c + 2] = v.z;
                KVs[r * 65 + c + 3] = v.w;
            }
        }
        if (tid < 64) {
            float mo = m_s[tid];
            float mx = mo;
            float* row = Ss + tid * 65;
            #pragma unroll 8
            for (int n = 0; n < 64; n++) mx = fmaxf(mx, row[n]);
            float alpha = __expf(mo - mx);     // -inf -> 0 on first tile
            float sum = 0.0f;
            #pragma unroll 8
            for (int n = 0; n < 64; n++) {
                float p = __expf(row[n] - mx); // -inf masked -> 0
                row[n] = p;
                sum += p;
            }
            m_s[tid] = mx;
            l_s[tid] = l_s[tid] * alpha + sum;
            al_s[tid] = alpha;
        }
        __syncthreads();

        // rescale accumulators, then O += P @ V
        float ar[4];
        #pragma unroll
        for (int r = 0; r < 4; r++) ar[r] = al_s[4 * ty + r];
        #pragma unroll
        for (int r = 0; r < 4; r++)
            #pragma unroll
            for (int c = 0; c < 4; c++)
                acc[r][c] *= ar[r];

        #pragma unroll 8
        for (int n = 0; n < 64; n++) {
            float p[4], vv[4];
            #pragma unroll
            for (int r = 0; r < 4; r++) p[r] = Ss[(4 * ty + r) * 65 + n];
            #pragma unroll
            for (int c = 0; c < 4; c++) vv[c] = KVs[n * 65 + 4 * tx + c];
            #pragma unroll
            for (int r = 0; r < 4; r++)
                #pragma unroll
                for (int c = 0; c < 4; c++)
                    acc[r][c] += p[r] * vv[c];
        }
        __syncthreads();  // protect KVs/Ss before next iteration
    }

    // epilogue: normalize and write y[b, t, h*64 + d]
    #pragma unroll
    for (int r = 0; r < 4; r++) {
        int row = 4 * ty + r;
        float inv = 1.0f / l_s[row];
        float4 o;
        o.x = acc[r][0] * inv;
        o.y = acc[r][1] * inv;
        o.z = acc[r][2] * inv;
        o.w = acc[r][3] * inv;
        size_t gtok = (size_t)b * T_SZ + qt * 64 + row;
        *(float4*)(y + gtok * C_SZ + h * HD + 4 * tx) = o;
    }
}

// ---------------------------------------------------------------------------
// Launch
// ---------------------------------------------------------------------------
extern "C" void kernel_launch(void* const* d_in, const int* in_sizes, int n_in,
                              void* d_out, int out_size)
{
    const float* x      = (const float*)d_in[0];
    const float* w_attn = (const float*)d_in[1];
    const float* b_attn = (const float*)d_in[2];
    const float* w_proj = (const float*)d_in[3];
    const float* b_proj = (const float*)d_in[4];
    float* out = (float*)d_out;

    float *qkv = nullptr, *y = nullptr;
    cudaGetSymbolAddress((void**)&qkv, g_qkv);
    cudaGetSymbolAddress((void**)&y, g_y);

    cudaFuncSetAttribute(flash_attn_kernel,
                         cudaFuncAttributeMaxDynamicSharedMemorySize,
                         SMEM_ATTN_BYTES);

    // 1) qkv = x @ w_attn + b_attn   [8192, 3072]
    {
        dim3 grid(3 * C_SZ / 64, MTOK / 64);
        gemm_bias_kernel<<<grid, 256>>>(x, w_attn, b_attn, qkv,
                                        MTOK, 3 * C_SZ, C_SZ);
    }
    // 2) RoPE in place on q, k
    {
        int total = MTOK * NH * 32;
        rope_kernel<<<total / 256, 256>>>(qkv);
    }
    // 3) flash attention -> y [8192, 1024]
    {
        dim3 grid(T_SZ / 64, NH, B_SZ);
        flash_attn_kernel<<<grid, 256, SMEM_ATTN_BYTES>>>(qkv, y);
    }
    // 4) out = y @ w_proj + b_proj   [8192, 1024]
    {
        dim3 grid(C_SZ / 64, MTOK / 64);
        gemm_bias_kernel<<<grid, 256>>>(y, w_proj, b_proj, out,
                                        MTOK, C_SZ, C_SZ);
    }
}

// round 2
// speedup vs baseline: 1.7379x; 1.7379x over previous
#include <cuda_runtime.h>
#include <math.h>
#include <stdint.h>

// Problem constants
#define B_SZ 4
#define T_SZ 2048
#define C_SZ 1024
#define NH   16
#define HD   64
#define MTOK (B_SZ * T_SZ)          // 8192 tokens
#define QKV_STRIDE (3 * C_SZ)       // 3072

// Scratch (device globals — no allocations allowed)
__device__ float g_qkv[(size_t)MTOK * QKV_STRIDE];  // 96 MB
__device__ float g_y[(size_t)MTOK * C_SZ];          // 32 MB

// ---------------------------------------------------------------------------
// TF32 tensor-core GEMM with bias: C[M,N] = A[M,K] @ B[K,N] + bias[N]
// Block tile 128x128, K-tile 32. 256 threads = 8 warps, warp grid 2(m)x4(n),
// each warp computes 64x32 via m16n8k8 tf32 mma.sync (4 m-frags x 4 n-frags
// x 4 k-steps). Inputs rounded with cvt.rna.tf32.f32 on the smem-store path;
// accumulation is exact fp32.
// Requires M%128==0, N%128==0, K%32==0 (true here).
// Smem bank check: a-frag addr=(row)*36+col -> bank=(4g+tig) bijective;
// b-frag addr=(k)*136+n -> bank=(8*tig+g) bijective. Conflict-free.
// ---------------------------------------------------------------------------
__device__ __forceinline__ uint32_t f32_to_tf32(float x) {
    uint32_t u;
    asm("cvt.rna.tf32.f32 %0, %1;" : "=r"(u) : "f"(x));
    return u;
}

__global__ __launch_bounds__(256, 2) void gemm_tf32_kernel(
    const float* __restrict__ A, const float* __restrict__ Bm,
    const float* __restrict__ bias, float* __restrict__ C,
    int M, int N, int K)
{
    __shared__ uint32_t As[128][36];   // [m][k] tf32 bits, pad 32->36
    __shared__ uint32_t Bs[32][136];   // [k][n] tf32 bits, pad 128->136

    const int tid  = threadIdx.x;
    const int wid  = tid >> 5;
    const int lane = tid & 31;
    const int g    = lane >> 2;     // groupID 0..7
    const int tig  = lane & 3;      // thread-in-group 0..3
    const int wm   = (wid & 1) * 64;   // warp m offset in tile
    const int wn   = (wid >> 1) * 32;  // warp n offset in tile

    const int bm = blockIdx.y * 128;
    const int bn = blockIdx.x * 128;

    // global-load coordinates
    const int a_row = tid >> 3;          // 0..31 (+32 per pass, 4 passes)
    const int a_col = (tid & 7) * 4;     // 0..28
    const int b_row = tid >> 5;          // 0..7 (+8 per pass, 4 passes)
    const int b_col = (lane) * 4;        // 0..124

    float acc[4][4][4] = {};             // [mi][ni][reg]
    float4 a_reg[4], b_reg[4];

    // prologue: load first k-tile to registers
    #pragma unroll
    for (int p = 0; p < 4; p++) {
        a_reg[p] = *(const float4*)(A + (size_t)(bm + a_row + 32 * p) * K + a_col);
        b_reg[p] = *(const float4*)(Bm + (size_t)(b_row + 8 * p) * N + bn + b_col);
    }

    for (int k0 = 0; k0 < K; k0 += 32) {
        // regs -> smem (with tf32 rounding)
        #pragma unroll
        for (int p = 0; p < 4; p++) {
            uint32_t* as = &As[a_row + 32 * p][a_col];
            as[0] = f32_to_tf32(a_reg[p].x);
            as[1] = f32_to_tf32(a_reg[p].y);
            as[2] = f32_to_tf32(a_reg[p].z);
            as[3] = f32_to_tf32(a_reg[p].w);
            uint32_t* bs = &Bs[b_row + 8 * p][b_col];
            bs[0] = f32_to_tf32(b_reg[p].x);
            bs[1] = f32_to_tf32(b_reg[p].y);
            bs[2] = f32_to_tf32(b_reg[p].z);
            bs[3] = f32_to_tf32(b_reg[p].w);
        }
        __syncthreads();

        // prefetch next k-tile
        if (k0 + 32 < K) {
            #pragma unroll
            for (int p = 0; p < 4; p++) {
                a_reg[p] = *(const float4*)(A + (size_t)(bm + a_row + 32 * p) * K + (k0 + 32) + a_col);
                b_reg[p] = *(const float4*)(Bm + (size_t)(k0 + 32 + b_row + 8 * p) * N + bn + b_col);
            }
        }

        // 4 k-steps of m16n8k8
        #pragma unroll
        for (int kk = 0; kk < 32; kk += 8) {
            uint32_t af[4][4];
            uint32_t bf[4][2];
            #pragma unroll
            for (int mi = 0; mi < 4; mi++) {
                int r = wm + 16 * mi + g;
                af[mi][0] = As[r][kk + tig];
                af[mi][1] = As[r + 8][kk + tig];
                af[mi][2] = As[r][kk + tig + 4];
                af[mi][3] = As[r + 8][kk + tig + 4];
            }
            #pragma unroll
            for (int ni = 0; ni < 4; ni++) {
                int cn = wn + 8 * ni + g;
                bf[ni][0] = Bs[kk + tig][cn];
                bf[ni][1] = Bs[kk + tig + 4][cn];
            }
            #pragma unroll
            for (int mi = 0; mi < 4; mi++)
                #pragma unroll
                for (int ni = 0; ni < 4; ni++) {
                    asm volatile(
                        "mma.sync.aligned.m16n8k8.row.col.f32.tf32.tf32.f32 "
                        "{%0,%1,%2,%3}, {%4,%5,%6,%7}, {%8,%9}, {%0,%1,%2,%3};"
                        : "+f"(acc[mi][ni][0]), "+f"(acc[mi][ni][1]),
                          "+f"(acc[mi][ni][2]), "+f"(acc[mi][ni][3])
                        : "r"(af[mi][0]), "r"(af[mi][1]), "r"(af[mi][2]), "r"(af[mi][3]),
                          "r"(bf[ni][0]), "r"(bf[ni][1]));
                }
        }
        __syncthreads();
    }

    // epilogue: bias + store. c0,c1: row=g, cols 2tig,2tig+1; c2,c3: row=g+8.
    #pragma unroll
    for (int ni = 0; ni < 4; ni++) {
        int col = bn + wn + 8 * ni + 2 * tig;
        float bx = bias[col], by = bias[col + 1];
        #pragma unroll
        for (int mi = 0; mi < 4; mi++) {
            int row0 = bm + wm + 16 * mi + g;
            float2 o0 = {acc[mi][ni][0] + bx, acc[mi][ni][1] + by};
            float2 o1 = {acc[mi][ni][2] + bx, acc[mi][ni][3] + by};
            *(float2*)(C + (size_t)row0 * N + col) = o0;
            *(float2*)(C + (size_t)(row0 + 8) * N + col) = o1;
        }
    }
}

// ---------------------------------------------------------------------------
// RoPE applied in-place to q and k inside the packed qkv buffer.
// ---------------------------------------------------------------------------
__global__ __launch_bounds__(256) void rope_kernel(float* __restrict__ qkv)
{
    int idx = blockIdx.x * blockDim.x + threadIdx.x;  // MTOK*NH*32 total
    int pair = idx & 31;
    int h    = (idx >> 5) & (NH - 1);
    int tok  = idx >> 9;                 // 0..MTOK-1
    int t    = tok & (T_SZ - 1);         // position within sequence

    float invf = powf(10000.0f, -(float)pair / 32.0f);
    float ang = (float)t * invf;
    float s, c;
    sincosf(ang, &s, &c);

    size_t base = (size_t)tok * QKV_STRIDE + h * HD;
    float* q = qkv + base;
    float* k = qkv + base + C_SZ;

    float q1 = q[pair], q2 = q[pair + 32];
    q[pair]      = q1 * c - q2 * s;
    q[pair + 32] = q2 * c + q1 * s;
    float k1 = k[pair], k2 = k[pair + 32];
    k[pair]      = k1 * c - k2 * s;
    k[pair + 32] = k2 * c + k1 * s;
}

// ---------------------------------------------------------------------------
// Flash attention (fp32, causal). Unchanged from round 1.
// ---------------------------------------------------------------------------
#define SM_QS   0
#define SM_KVS  (64 * 64)
#define SM_SS   (SM_KVS + 64 * 65)
#define SM_M    (SM_SS + 64 * 65)
#define SM_L    (SM_M + 64)
#define SM_AL   (SM_L + 64)
#define SMEM_ATTN_FLOATS (SM_AL + 64)
#define SMEM_ATTN_BYTES  (SMEM_ATTN_FLOATS * 4)

__global__ __launch_bounds__(256) void flash_attn_kernel(
    const float* __restrict__ qkv, float* __restrict__ y)
{
    extern __shared__ float sm[];
    float* Qs  = sm + SM_QS;
    float* KVs = sm + SM_KVS;
    float* Ss  = sm + SM_SS;
    float* m_s = sm + SM_M;
    float* l_s = sm + SM_L;
    float* al_s = sm + SM_AL;

    const int qt = blockIdx.x;          // 0..31
    const int h  = blockIdx.y;
    const int b  = blockIdx.z;
    const int tid = threadIdx.x;
    const int tx = tid & 15;
    const int ty = tid >> 4;

    const float* qbase = qkv + (size_t)b * T_SZ * QKV_STRIDE + h * HD;
    const float* kbase = qbase + C_SZ;
    const float* vbase = qbase + 2 * C_SZ;

    {
        int l = tid * 4;
        #pragma unroll
        for (int it = 0; it < 4; it++, l += 1024) {
            int r = l >> 6, c = l & 63;
            float4 v = *(const float4*)(qbase + (size_t)(qt * 64 + r) * QKV_STRIDE + c);
            Qs[r * 64 + c + 0] = v.x * 0.125f;
            Qs[r * 64 + c + 1] = v.y * 0.125f;
            Qs[r * 64 + c + 2] = v.z * 0.125f;
            Qs[r * 64 + c + 3] = v.w * 0.125f;
        }
    }
    if (tid < 64) { m_s[tid] = -INFINITY; l_s[tid] = 0.0f; }
    float acc[4][4] = {};
    __syncthreads();

    for (int kt = 0; kt <= qt; kt++) {
        {
            int l = tid * 4;
            #pragma unroll
            for (int it = 0; it < 4; it++, l += 1024) {
                int r = l >> 6, c = l & 63;
                float4 v = *(const float4*)(kbase + (size_t)(kt * 64 + r) * QKV_STRIDE + c);
                KVs[r * 65 + c + 0] = v.x;
                KVs[r * 65 + c + 1] = v.y;
                KVs[r * 65 + c + 2] = v.z;
                KVs[r * 65 + c + 3] = v.w;
            }
        }
        __syncthreads();

        float s[4][4] = {};
        #pragma unroll 8
        for (int d = 0; d < 64; d++) {
            float a[4], kv[4];
            #pragma unroll
            for (int r = 0; r < 4; r++) a[r] = Qs[(4 * ty + r) * 64 + d];
            #pragma unroll
            for (int c = 0; c < 4; c++) kv[c] = KVs[(4 * tx + c) * 65 + d];
            #pragma unroll
            for (int r = 0; r < 4; r++)
                #pragma unroll
                for (int c = 0; c < 4; c++)
                    s[r][c] += a[r] * kv[c];
        }
        const bool diag = (kt == qt);
        #pragma unroll
        for (int r = 0; r < 4; r++) {
            int qi = qt * 64 + 4 * ty + r;
            #pragma unroll
            for (int c = 0; c < 4; c++) {
                int kj = kt * 64 + 4 * tx + c;
                float v = s[r][c];
                if (diag && kj > qi) v = -INFINITY;
                Ss[(4 * ty + r) * 65 + 4 * tx + c] = v;
            }
        }
        __syncthreads();

        {
            int l = tid * 4;
            #pragma unroll
            for (int it = 0; it < 4; it++, l += 1024) {
                int r = l >> 6, c = l & 63;
                float4 v = *(const float4*)(vbase + (size_t)(kt * 64 + r) * QKV_STRIDE + c);
                KVs[r * 65 + c + 0] = v.x;
                KVs[r * 65 + c + 1] = v.y;
                KVs[r * 65 + c + 2] = v.z;
                KVs[r * 65 + c + 3] = v.w;
            }
        }
        if (tid < 64) {
            float mo = m_s[tid];
            float mx = mo;
            float* row = Ss + tid * 65;
            #pragma unroll 8
            for (int n = 0; n < 64; n++) mx = fmaxf(mx, row[n]);
            float alpha = __expf(mo - mx);
            float sum = 0.0f;
            #pragma unroll 8
            for (int n = 0; n < 64; n++) {
                float p = __expf(row[n] - mx);
                row[n] = p;
                sum += p;
            }
            m_s[tid] = mx;
            l_s[tid] = l_s[tid] * alpha + sum;
            al_s[tid] = alpha;
        }
        __syncthreads();

        float ar[4];
        #pragma unroll
        for (int r = 0; r < 4; r++) ar[r] = al_s[4 * ty + r];
        #pragma unroll
        for (int r = 0; r < 4; r++)
            #pragma unroll
            for (int c = 0; c < 4; c++)
                acc[r][c] *= ar[r];

        #pragma unroll 8
        for (int n = 0; n < 64; n++) {
            float p[4], vv[4];
            #pragma unroll
            for (int r = 0; r < 4; r++) p[r] = Ss[(4 * ty + r) * 65 + n];
            #pragma unroll
            for (int c = 0; c < 4; c++) vv[c] = KVs[n * 65 + 4 * tx + c];
            #pragma unroll
            for (int r = 0; r < 4; r++)
                #pragma unroll
                for (int c = 0; c < 4; c++)
                    acc[r][c] += p[r] * vv[c];
        }
        __syncthreads();
    }

    #pragma unroll
    for (int r = 0; r < 4; r++) {
        int row = 4 * ty + r;
        float inv = 1.0f / l_s[row];
        float4 o;
        o.x = acc[r][0] * inv;
        o.y = acc[r][1] * inv;
        o.z = acc[r][2] * inv;
        o.w = acc[r][3] * inv;
        size_t gtok = (size_t)b * T_SZ + qt * 64 + row;
        *(float4*)(y + gtok * C_SZ + h * HD + 4 * tx) = o;
    }
}

// ---------------------------------------------------------------------------
// Launch
// ---------------------------------------------------------------------------
extern "C" void kernel_launch(void* const* d_in, const int* in_sizes, int n_in,
                              void* d_out, int out_size)
{
    const float* x      = (const float*)d_in[0];
    const float* w_attn = (const float*)d_in[1];
    const float* b_attn = (const float*)d_in[2];
    const float* w_proj = (const float*)d_in[3];
    const float* b_proj = (const float*)d_in[4];
    float* out = (float*)d_out;

    float *qkv = nullptr, *y = nullptr;
    cudaGetSymbolAddress((void**)&qkv, g_qkv);
    cudaGetSymbolAddress((void**)&y, g_y);

    cudaFuncSetAttribute(flash_attn_kernel,
                         cudaFuncAttributeMaxDynamicSharedMemorySize,
                         SMEM_ATTN_BYTES);

    // 1) qkv = x @ w_attn + b_attn   [8192, 3072]
    {
        dim3 grid(3 * C_SZ / 128, MTOK / 128);
        gemm_tf32_kernel<<<grid, 256>>>(x, w_attn, b_attn, qkv,
                                        MTOK, 3 * C_SZ, C_SZ);
    }
    // 2) RoPE in place on q, k
    {
        int total = MTOK * NH * 32;
        rope_kernel<<<total / 256, 256>>>(qkv);
    }
    // 3) flash attention -> y [8192, 1024]
    {
        dim3 grid(T_SZ / 64, NH, B_SZ);
        flash_attn_kernel<<<grid, 256, SMEM_ATTN_BYTES>>>(qkv, y);
    }
    // 4) out = y @ w_proj + b_proj   [8192, 1024]
    {
        dim3 grid(C_SZ / 128, MTOK / 128);
        gemm_tf32_kernel<<<grid, 256>>>(y, w_proj, b_proj, out,
                                        MTOK, C_SZ, C_SZ);
    }
}

// round 3
// speedup vs baseline: 3.2591x; 1.8753x over previous
#include <cuda_runtime.h>
#include <math.h>
#include <stdint.h>

// Problem constants
#define B_SZ 4
#define T_SZ 2048
#define C_SZ 1024
#define NH   16
#define HD   64
#define MTOK (B_SZ * T_SZ)          // 8192 tokens
#define QKV_STRIDE (3 * C_SZ)       // 3072

// Scratch (device globals — no allocations allowed)
__device__ float g_qkv[(size_t)MTOK * QKV_STRIDE];  // 96 MB
__device__ float g_y[(size_t)MTOK * C_SZ];          // 32 MB

__device__ __forceinline__ uint32_t f32_to_tf32(float x) {
    uint32_t u;
    asm("cvt.rna.tf32.f32 %0, %1;" : "=r"(u) : "f"(x));
    return u;
}

__device__ __forceinline__ void mma_tf32(float c[4],
    uint32_t a0, uint32_t a1, uint32_t a2, uint32_t a3,
    uint32_t b0, uint32_t b1)
{
    asm volatile(
        "mma.sync.aligned.m16n8k8.row.col.f32.tf32.tf32.f32 "
        "{%0,%1,%2,%3}, {%4,%5,%6,%7}, {%8,%9}, {%0,%1,%2,%3};"
        : "+f"(c[0]), "+f"(c[1]), "+f"(c[2]), "+f"(c[3])
        : "r"(a0), "r"(a1), "r"(a2), "r"(a3), "r"(b0), "r"(b1));
}

// ---------------------------------------------------------------------------
// TF32 tensor-core GEMM with bias (unchanged from round 2).
// ---------------------------------------------------------------------------
__global__ __launch_bounds__(256, 2) void gemm_tf32_kernel(
    const float* __restrict__ A, const float* __restrict__ Bm,
    const float* __restrict__ bias, float* __restrict__ C,
    int M, int N, int K)
{
    __shared__ uint32_t As[128][36];
    __shared__ uint32_t Bs[32][136];

    const int tid  = threadIdx.x;
    const int wid  = tid >> 5;
    const int lane = tid & 31;
    const int g    = lane >> 2;
    const int tig  = lane & 3;
    const int wm   = (wid & 1) * 64;
    const int wn   = (wid >> 1) * 32;

    const int bm = blockIdx.y * 128;
    const int bn = blockIdx.x * 128;

    const int a_row = tid >> 3;
    const int a_col = (tid & 7) * 4;
    const int b_row = tid >> 5;
    const int b_col = (lane) * 4;

    float acc[4][4][4] = {};
    float4 a_reg[4], b_reg[4];

    #pragma unroll
    for (int p = 0; p < 4; p++) {
        a_reg[p] = *(const float4*)(A + (size_t)(bm + a_row + 32 * p) * K + a_col);
        b_reg[p] = *(const float4*)(Bm + (size_t)(b_row + 8 * p) * N + bn + b_col);
    }

    for (int k0 = 0; k0 < K; k0 += 32) {
        #pragma unroll
        for (int p = 0; p < 4; p++) {
            uint32_t* as = &As[a_row + 32 * p][a_col];
            as[0] = f32_to_tf32(a_reg[p].x);
            as[1] = f32_to_tf32(a_reg[p].y);
            as[2] = f32_to_tf32(a_reg[p].z);
            as[3] = f32_to_tf32(a_reg[p].w);
            uint32_t* bs = &Bs[b_row + 8 * p][b_col];
            bs[0] = f32_to_tf32(b_reg[p].x);
            bs[1] = f32_to_tf32(b_reg[p].y);
            bs[2] = f32_to_tf32(b_reg[p].z);
            bs[3] = f32_to_tf32(b_reg[p].w);
        }
        __syncthreads();

        if (k0 + 32 < K) {
            #pragma unroll
            for (int p = 0; p < 4; p++) {
                a_reg[p] = *(const float4*)(A + (size_t)(bm + a_row + 32 * p) * K + (k0 + 32) + a_col);
                b_reg[p] = *(const float4*)(Bm + (size_t)(k0 + 32 + b_row + 8 * p) * N + bn + b_col);
            }
        }

        #pragma unroll
        for (int kk = 0; kk < 32; kk += 8) {
            uint32_t af[4][4];
            uint32_t bf[4][2];
            #pragma unroll
            for (int mi = 0; mi < 4; mi++) {
                int r = wm + 16 * mi + g;
                af[mi][0] = As[r][kk + tig];
                af[mi][1] = As[r + 8][kk + tig];
                af[mi][2] = As[r][kk + tig + 4];
                af[mi][3] = As[r + 8][kk + tig + 4];
            }
            #pragma unroll
            for (int ni = 0; ni < 4; ni++) {
                int cn = wn + 8 * ni + g;
                bf[ni][0] = Bs[kk + tig][cn];
                bf[ni][1] = Bs[kk + tig + 4][cn];
            }
            #pragma unroll
            for (int mi = 0; mi < 4; mi++)
                #pragma unroll
                for (int ni = 0; ni < 4; ni++)
                    mma_tf32(acc[mi][ni], af[mi][0], af[mi][1], af[mi][2], af[mi][3],
                             bf[ni][0], bf[ni][1]);
        }
        __syncthreads();
    }

    #pragma unroll
    for (int ni = 0; ni < 4; ni++) {
        int col = bn + wn + 8 * ni + 2 * tig;
        float bx = bias[col], by = bias[col + 1];
        #pragma unroll
        for (int mi = 0; mi < 4; mi++) {
            int row0 = bm + wm + 16 * mi + g;
            float2 o0 = {acc[mi][ni][0] + bx, acc[mi][ni][1] + by};
            float2 o1 = {acc[mi][ni][2] + bx, acc[mi][ni][3] + by};
            *(float2*)(C + (size_t)row0 * N + col) = o0;
            *(float2*)(C + (size_t)(row0 + 8) * N + col) = o1;
        }
    }
}

// ---------------------------------------------------------------------------
// RoPE (unchanged)
// ---------------------------------------------------------------------------
__global__ __launch_bounds__(256) void rope_kernel(float* __restrict__ qkv)
{
    int idx = blockIdx.x * blockDim.x + threadIdx.x;
    int pair = idx & 31;
    int h    = (idx >> 5) & (NH - 1);
    int tok  = idx >> 9;
    int t    = tok & (T_SZ - 1);

    float invf = powf(10000.0f, -(float)pair / 32.0f);
    float ang = (float)t * invf;
    float s, c;
    sincosf(ang, &s, &c);

    size_t base = (size_t)tok * QKV_STRIDE + h * HD;
    float* q = qkv + base;
    float* k = qkv + base + C_SZ;

    float q1 = q[pair], q2 = q[pair + 32];
    q[pair]      = q1 * c - q2 * s;
    q[pair + 32] = q2 * c + q1 * s;
    float k1 = k[pair], k2 = k[pair + 32];
    k[pair]      = k1 * c - k2 * s;
    k[pair + 32] = k2 * c + k1 * s;
}

// ---------------------------------------------------------------------------
// TF32 tensor-core flash attention (causal).
// Block: 128 q rows, 256 threads = 8 warps, warp w owns rows [16w,16w+16).
// kv tiles of 64. Per warp: S(16x64) via m16n8k8, in-register online softmax
// (quad shuffles), P -> smem (per-warp region, __syncwarp), PV via mma.
// Smem rows padded to 68 u32 (68 mod 32 == 4 -> fragment LDS conflict-free).
// ---------------------------------------------------------------------------
#define FA_PAD 68
#define FQ 0
#define FK (128 * FA_PAD)
#define FV (FK + 64 * FA_PAD)
#define FP (FV + 64 * FA_PAD)
#define FA_SMEM_U32 (FP + 128 * FA_PAD)
#define FA_SMEM_BYTES (FA_SMEM_U32 * 4)

__global__ __launch_bounds__(256) void flash_tf32_kernel(
    const float* __restrict__ qkv, float* __restrict__ y)
{
    extern __shared__ uint32_t fsm[];
    uint32_t* Qs = fsm + FQ;
    uint32_t* Ks = fsm + FK;
    uint32_t* Vt = fsm + FV;
    uint32_t* Ps = fsm + FP;

    const int qt = blockIdx.x;          // 0..15
    const int h  = blockIdx.y;
    const int b  = blockIdx.z;
    const int tid  = threadIdx.x;
    const int w    = tid >> 5;
    const int lane = tid & 31;
    const int g    = lane >> 2;
    const int tig  = lane & 3;

    const float* qbase = qkv + (size_t)b * T_SZ * QKV_STRIDE + h * HD;
    const float* kbase = qbase + C_SZ;
    const float* vbase = qbase + 2 * C_SZ;

    // load Q (128x64), scale 1/8, tf32
    {
        int r = tid >> 4, c = (tid & 15) * 4;
        #pragma unroll
        for (int p = 0; p < 8; p++) {
            float4 v = *(const float4*)(qbase + (size_t)(qt * 128 + r + 16 * p) * QKV_STRIDE + c);
            uint32_t* dst = Qs + (size_t)(r + 16 * p) * FA_PAD + c;
            dst[0] = f32_to_tf32(v.x * 0.125f);
            dst[1] = f32_to_tf32(v.y * 0.125f);
            dst[2] = f32_to_tf32(v.z * 0.125f);
            dst[3] = f32_to_tf32(v.w * 0.125f);
        }
    }

    float m0 = -INFINITY, m1 = -INFINITY, l0 = 0.0f, l1 = 0.0f;
    float o[8][4] = {};

    const int row0 = qt * 128 + 16 * w + g;   // rows for c0/c1
    const int row1 = row0 + 8;                // rows for c2/c3
    const int wrow_lo = qt * 128 + 16 * w;    // warp's lowest row
    const int ktmax = 2 * qt + 1;

    for (int kt = 0; kt <= ktmax; kt++) {
        // load K tile (64x64) -> Ks[kv][d]
        {
            int r = tid >> 4, c = (tid & 15) * 4;
            #pragma unroll
            for (int p = 0; p < 4; p++) {
                float4 v = *(const float4*)(kbase + (size_t)(kt * 64 + r + 16 * p) * QKV_STRIDE + c);
                uint32_t* dst = Ks + (r + 16 * p) * FA_PAD + c;
                dst[0] = f32_to_tf32(v.x);
                dst[1] = f32_to_tf32(v.y);
                dst[2] = f32_to_tf32(v.z);
                dst[3] = f32_to_tf32(v.w);
            }
        }
        // load V tile transposed -> Vt[d][kv]
        {
            int r = tid >> 4, c = (tid & 15) * 4;
            #pragma unroll
            for (int p = 0; p < 4; p++) {
                int rr = r + 16 * p;
                float4 v = *(const float4*)(vbase + (size_t)(kt * 64 + rr) * QKV_STRIDE + c);
                Vt[(c + 0) * FA_PAD + rr] = f32_to_tf32(v.x);
                Vt[(c + 1) * FA_PAD + rr] = f32_to_tf32(v.y);
                Vt[(c + 2) * FA_PAD + rr] = f32_to_tf32(v.z);
                Vt[(c + 3) * FA_PAD + rr] = f32_to_tf32(v.w);
            }
        }
        __syncthreads();

        const bool active = (kt * 64 <= wrow_lo + 15);
        if (active) {
            // S = Q @ K^T
            float s[8][4] = {};
            const uint32_t* qw = Qs + (16 * w) * FA_PAD;
            #pragma unroll
            for (int kk = 0; kk < 64; kk += 8) {
                uint32_t a0 = qw[g * FA_PAD + kk + tig];
                uint32_t a1 = qw[(g + 8) * FA_PAD + kk + tig];
                uint32_t a2 = qw[g * FA_PAD + kk + tig + 4];
                uint32_t a3 = qw[(g + 8) * FA_PAD + kk + tig + 4];
                #pragma unroll
                for (int ni = 0; ni < 8; ni++) {
                    const uint32_t* kr = Ks + (8 * ni + g) * FA_PAD + kk + tig;
                    mma_tf32(s[ni], a0, a1, a2, a3, kr[0], kr[4]);
                }
            }

            // causal mask (only tiles overlapping the diagonal)
            if (kt * 64 + 63 > wrow_lo) {
                #pragma unroll
                for (int ni = 0; ni < 8; ni++) {
                    int col = kt * 64 + 8 * ni + 2 * tig;
                    if (col     > row0) s[ni][0] = -INFINITY;
                    if (col + 1 > row0) s[ni][1] = -INFINITY;
                    if (col     > row1) s[ni][2] = -INFINITY;
                    if (col + 1 > row1) s[ni][3] = -INFINITY;
                }
            }

            // row max (in-thread over 16 vals, then quad shuffle)
            float mx0 = s[0][0], mx1 = s[0][2];
            #pragma unroll
            for (int ni = 0; ni < 8; ni++) {
                mx0 = fmaxf(mx0, fmaxf(s[ni][0], s[ni][1]));
                mx1 = fmaxf(mx1, fmaxf(s[ni][2], s[ni][3]));
            }
            mx0 = fmaxf(mx0, __shfl_xor_sync(0xffffffffu, mx0, 1));
            mx0 = fmaxf(mx0, __shfl_xor_sync(0xffffffffu, mx0, 2));
            mx1 = fmaxf(mx1, __shfl_xor_sync(0xffffffffu, mx1, 1));
            mx1 = fmaxf(mx1, __shfl_xor_sync(0xffffffffu, mx1, 2));

            float mn0 = fmaxf(m0, mx0), mn1 = fmaxf(m1, mx1);
            float al0 = __expf(m0 - mn0), al1 = __expf(m1 - mn1);

            // exp + row sum + store P (tf32) to per-warp smem region
            uint32_t* pw0 = Ps + (16 * w + g) * FA_PAD + 2 * tig;
            uint32_t* pw1 = Ps + (16 * w + g + 8) * FA_PAD + 2 * tig;
            float r0 = 0.0f, r1 = 0.0f;
            #pragma unroll
            for (int ni = 0; ni < 8; ni++) {
                float p0 = __expf(s[ni][0] - mn0);
                float p1 = __expf(s[ni][1] - mn0);
                float p2 = __expf(s[ni][2] - mn1);
                float p3 = __expf(s[ni][3] - mn1);
                r0 += p0 + p1;
                r1 += p2 + p3;
                pw0[8 * ni]     = f32_to_tf32(p0);
                pw0[8 * ni + 1] = f32_to_tf32(p1);
                pw1[8 * ni]     = f32_to_tf32(p2);
                pw1[8 * ni + 1] = f32_to_tf32(p3);
            }
            r0 += __shfl_xor_sync(0xffffffffu, r0, 1);
            r0 += __shfl_xor_sync(0xffffffffu, r0, 2);
            r1 += __shfl_xor_sync(0xffffffffu, r1, 1);
            r1 += __shfl_xor_sync(0xffffffffu, r1, 2);

            l0 = l0 * al0 + r0;
            l1 = l1 * al1 + r1;
            m0 = mn0;
            m1 = mn1;

            // rescale O accumulators
            #pragma unroll
            for (int ni = 0; ni < 8; ni++) {
                o[ni][0] *= al0; o[ni][1] *= al0;
                o[ni][2] *= al1; o[ni][3] *= al1;
            }

            __syncwarp();

            // O += P @ V  (A-frags from Ps, B-frags from Vt)
            const uint32_t* psw = Ps + (16 * w) * FA_PAD;
            #pragma unroll
            for (int kk = 0; kk < 64; kk += 8) {
                uint32_t a0 = psw[g * FA_PAD + kk + tig];
                uint32_t a1 = psw[(g + 8) * FA_PAD + kk + tig];
                uint32_t a2 = psw[g * FA_PAD + kk + tig + 4];
                uint32_t a3 = psw[(g + 8) * FA_PAD + kk + tig + 4];
                #pragma unroll
                for (int ni = 0; ni < 8; ni++) {
                    const uint32_t* vr = Vt + (8 * ni + g) * FA_PAD + kk + tig;
                    mma_tf32(o[ni], a0, a1, a2, a3, vr[0], vr[4]);
                }
            }
        }
        __syncthreads();
    }

    // epilogue: normalize and store
    float inv0 = 1.0f / l0, inv1 = 1.0f / l1;
    #pragma unroll
    for (int ni = 0; ni < 8; ni++) {
        int col = h * HD + 8 * ni + 2 * tig;
        float2 o0 = {o[ni][0] * inv0, o[ni][1] * inv0};
        float2 o1 = {o[ni][2] * inv1, o[ni][3] * inv1};
        *(float2*)(y + ((size_t)b * T_SZ + row0) * C_SZ + col) = o0;
        *(float2*)(y + ((size_t)b * T_SZ + row1) * C_SZ + col) = o1;
    }
}

// ---------------------------------------------------------------------------
// Launch
// ---------------------------------------------------------------------------
extern "C" void kernel_launch(void* const* d_in, const int* in_sizes, int n_in,
                              void* d_out, int out_size)
{
    const float* x      = (const float*)d_in[0];
    const float* w_attn = (const float*)d_in[1];
    const float* b_attn = (const float*)d_in[2];
    const float* w_proj = (const float*)d_in[3];
    const float* b_proj = (const float*)d_in[4];
    float* out = (float*)d_out;

    float *qkv = nullptr, *y = nullptr;
    cudaGetSymbolAddress((void**)&qkv, g_qkv);
    cudaGetSymbolAddress((void**)&y, g_y);

    cudaFuncSetAttribute(flash_tf32_kernel,
                         cudaFuncAttributeMaxDynamicSharedMemorySize,
                         FA_SMEM_BYTES);

    // 1) qkv = x @ w_attn + b_attn   [8192, 3072]
    {
        dim3 grid(3 * C_SZ / 128, MTOK / 128);
        gemm_tf32_kernel<<<grid, 256>>>(x, w_attn, b_attn, qkv,
                                        MTOK, 3 * C_SZ, C_SZ);
    }
    // 2) RoPE in place on q, k
    {
        int total = MTOK * NH * 32;
        rope_kernel<<<total / 256, 256>>>(qkv);
    }
    // 3) flash attention -> y [8192, 1024]
    {
        dim3 grid(T_SZ / 128, NH, B_SZ);
        flash_tf32_kernel<<<grid, 256, FA_SMEM_BYTES>>>(qkv, y);
    }
    // 4) out = y @ w_proj + b_proj   [8192, 1024]
    {
        dim3 grid(C_SZ / 128, MTOK / 128);
        gemm_tf32_kernel<<<grid, 256>>>(y, w_proj, b_proj, out,
                                        MTOK, C_SZ, C_SZ);
    }
}

// round 4
// speedup vs baseline: 3.4543x; 1.0599x over previous
#include <cuda_runtime.h>
#include <math.h>
#include <stdint.h>

// Problem constants
#define B_SZ 4
#define T_SZ 2048
#define C_SZ 1024
#define NH   16
#define HD   64
#define MTOK (B_SZ * T_SZ)
#define QKV_STRIDE (3 * C_SZ)

__device__ float g_qkv[(size_t)MTOK * QKV_STRIDE];  // 96 MB
__device__ float g_y[(size_t)MTOK * C_SZ];          // 32 MB

__device__ __forceinline__ uint32_t f32_to_tf32(float x) {
    uint32_t u;
    asm("cvt.rna.tf32.f32 %0, %1;" : "=r"(u) : "f"(x));
    return u;
}

__device__ __forceinline__ void mma_tf32(float c[4],
    uint32_t a0, uint32_t a1, uint32_t a2, uint32_t a3,
    uint32_t b0, uint32_t b1)
{
    asm volatile(
        "mma.sync.aligned.m16n8k8.row.col.f32.tf32.tf32.f32 "
        "{%0,%1,%2,%3}, {%4,%5,%6,%7}, {%8,%9}, {%0,%1,%2,%3};"
        : "+f"(c[0]), "+f"(c[1]), "+f"(c[2]), "+f"(c[3])
        : "r"(a0), "r"(a1), "r"(a2), "r"(a3), "r"(b0), "r"(b1));
}

__device__ __forceinline__ void cp16(void* smem, const void* g) {
    uint32_t s = (uint32_t)__cvta_generic_to_shared(smem);
    asm volatile("cp.async.cg.shared.global [%0], [%1], 16;" :: "r"(s), "l"(g));
}
#define CP_COMMIT() asm volatile("cp.async.commit_group;")

// ---------------------------------------------------------------------------
// TF32 GEMM, 128x128 tile, K-tile 32, 128 threads = 4 warps, warp tile 64x64.
// cp.async double-buffered smem (raw fp32), cvt.rna post-LDS.
// Stage layout (u32/f32 units): As[128][36], Bs[32][136]  -> 8960 per stage.
// ---------------------------------------------------------------------------
#define G_AS_PAD 36
#define G_BS_PAD 136
#define G_STAGE (128 * G_AS_PAD + 32 * G_BS_PAD)   // 8960
#define G_SMEM_BYTES (2 * G_STAGE * 4)             // 71680

__global__ __launch_bounds__(128) void gemm_tf32_kernel(
    const float* __restrict__ A, const float* __restrict__ Bm,
    const float* __restrict__ bias, float* __restrict__ C,
    int M, int N, int K)
{
    extern __shared__ float gsm[];

    const int tid  = threadIdx.x;
    const int wid  = tid >> 5;
    const int lane = tid & 31;
    const int g    = lane >> 2;
    const int tig  = lane & 3;
    const int wm   = (wid & 1) * 64;
    const int wn   = (wid >> 1) * 64;

    const int bm = blockIdx.y * 128;
    const int bn = blockIdx.x * 128;

    // copy coords
    const int a_r = tid >> 3;          // 0..15, +16 per pass (8 passes)
    const int a_c = (tid & 7) * 4;
    const int b_r = tid >> 5;          // 0..3, +4 per pass (8 passes)
    const int b_c = lane * 4;

    float acc[4][8][4] = {};

    // prologue: stage 0
    {
        float* As_ = gsm;
        float* Bs_ = gsm + 128 * G_AS_PAD;
        #pragma unroll
        for (int p = 0; p < 8; p++) {
            cp16(&As_[(a_r + 16 * p) * G_AS_PAD + a_c],
                 A + (size_t)(bm + a_r + 16 * p) * K + a_c);
            cp16(&Bs_[(b_r + 4 * p) * G_BS_PAD + b_c],
                 Bm + (size_t)(b_r + 4 * p) * N + bn + b_c);
        }
        CP_COMMIT();
    }

    const int NT = K >> 5;
    for (int kt = 0; kt < NT; kt++) {
        if (kt + 1 < NT) {
            float* As_ = gsm + ((kt + 1) & 1) * G_STAGE;
            float* Bs_ = As_ + 128 * G_AS_PAD;
            const int k0 = (kt + 1) * 32;
            #pragma unroll
            for (int p = 0; p < 8; p++) {
                cp16(&As_[(a_r + 16 * p) * G_AS_PAD + a_c],
                     A + (size_t)(bm + a_r + 16 * p) * K + k0 + a_c);
                cp16(&Bs_[(b_r + 4 * p) * G_BS_PAD + b_c],
                     Bm + (size_t)(k0 + b_r + 4 * p) * N + bn + b_c);
            }
            CP_COMMIT();
            asm volatile("cp.async.wait_group 1;");
        } else {
            asm volatile("cp.async.wait_group 0;");
        }
        __syncthreads();

        const float* As_ = gsm + (kt & 1) * G_STAGE;
        const float* Bs_ = As_ + 128 * G_AS_PAD;

        #pragma unroll
        for (int kk = 0; kk < 32; kk += 8) {
            uint32_t af[4][4];
            #pragma unroll
            for (int mi = 0; mi < 4; mi++) {
                int r = wm + 16 * mi + g;
                af[mi][0] = f32_to_tf32(As_[r * G_AS_PAD + kk + tig]);
                af[mi][1] = f32_to_tf32(As_[(r + 8) * G_AS_PAD + kk + tig]);
                af[mi][2] = f32_to_tf32(As_[r * G_AS_PAD + kk + tig + 4]);
                af[mi][3] = f32_to_tf32(As_[(r + 8) * G_AS_PAD + kk + tig + 4]);
            }
            #pragma unroll
            for (int ni = 0; ni < 8; ni++) {
                int cn = wn + 8 * ni + g;
                uint32_t b0 = f32_to_tf32(Bs_[(kk + tig) * G_BS_PAD + cn]);
                uint32_t b1 = f32_to_tf32(Bs_[(kk + tig + 4) * G_BS_PAD + cn]);
                #pragma unroll
                for (int mi = 0; mi < 4; mi++)
                    mma_tf32(acc[mi][ni], af[mi][0], af[mi][1], af[mi][2], af[mi][3],
                             b0, b1);
            }
        }
        __syncthreads();
    }

    // epilogue
    #pragma unroll
    for (int ni = 0; ni < 8; ni++) {
        int col = bn + wn + 8 * ni + 2 * tig;
        float bx = bias[col], by = bias[col + 1];
        #pragma unroll
        for (int mi = 0; mi < 4; mi++) {
            int row0 = bm + wm + 16 * mi + g;
            float2 o0 = {acc[mi][ni][0] + bx, acc[mi][ni][1] + by};
            float2 o1 = {acc[mi][ni][2] + bx, acc[mi][ni][3] + by};
            *(float2*)(C + (size_t)row0 * N + col) = o0;
            *(float2*)(C + (size_t)(row0 + 8) * N + col) = o1;
        }
    }
}

// ---------------------------------------------------------------------------
// RoPE (unchanged)
// ---------------------------------------------------------------------------
__global__ __launch_bounds__(256) void rope_kernel(float* __restrict__ qkv)
{
    int idx = blockIdx.x * blockDim.x + threadIdx.x;
    int pair = idx & 31;
    int h    = (idx >> 5) & (NH - 1);
    int tok  = idx >> 9;
    int t    = tok & (T_SZ - 1);

    float invf = powf(10000.0f, -(float)pair / 32.0f);
    float ang = (float)t * invf;
    float s, c;
    sincosf(ang, &s, &c);

    size_t base = (size_t)tok * QKV_STRIDE + h * HD;
    float* q = qkv + base;
    float* k = qkv + base + C_SZ;

    float q1 = q[pair], q2 = q[pair + 32];
    q[pair]      = q1 * c - q2 * s;
    q[pair + 32] = q2 * c + q1 * s;
    float k1 = k[pair], k2 = k[pair + 32];
    k[pair]      = k1 * c - k2 * s;
    k[pair + 32] = k2 * c + k1 * s;
}

// ---------------------------------------------------------------------------
// TF32 flash attention (causal). BM=128, 128 threads = 4 warps, warp tile
// 32 q-rows x 64 kv. Online softmax in registers (quad shuffles); P via
// per-warp smem round trip.
// ---------------------------------------------------------------------------
#define FA_PAD 68
#define FQ 0
#define FK (128 * FA_PAD)
#define FV (FK + 64 * FA_PAD)
#define FP (FV + 64 * FA_PAD)
#define FA_SMEM_U32 (FP + 128 * FA_PAD)
#define FA_SMEM_BYTES (FA_SMEM_U32 * 4)

__global__ __launch_bounds__(128) void flash_tf32_kernel(
    const float* __restrict__ qkv, float* __restrict__ y)
{
    extern __shared__ uint32_t fsm[];
    uint32_t* Qs = fsm + FQ;
    uint32_t* Ks = fsm + FK;
    uint32_t* Vt = fsm + FV;
    uint32_t* Ps = fsm + FP;

    const int qt = blockIdx.x;
    const int h  = blockIdx.y;
    const int b  = blockIdx.z;
    const int tid  = threadIdx.x;
    const int w    = tid >> 5;
    const int lane = tid & 31;
    const int g    = lane >> 2;
    const int tig  = lane & 3;

    const float* qbase = qkv + (size_t)b * T_SZ * QKV_STRIDE + h * HD;
    const float* kbase = qbase + C_SZ;
    const float* vbase = qbase + 2 * C_SZ;

    // load Q (128x64), scale 1/8, tf32. 128 threads, 16 float4 each.
    {
        int r = tid >> 4, c = (tid & 15) * 4;
        #pragma unroll
        for (int p = 0; p < 16; p++) {
            int rr = r + 8 * p;
            float4 v = *(const float4*)(qbase + (size_t)(qt * 128 + rr) * QKV_STRIDE + c);
            uint32_t* dst = Qs + rr * FA_PAD + c;
            dst[0] = f32_to_tf32(v.x * 0.125f);
            dst[1] = f32_to_tf32(v.y * 0.125f);
            dst[2] = f32_to_tf32(v.z * 0.125f);
            dst[3] = f32_to_tf32(v.w * 0.125f);
        }
    }

    float m[2][2], l[2][2];
    #pragma unroll
    for (int mi = 0; mi < 2; mi++) {
        m[mi][0] = -INFINITY; m[mi][1] = -INFINITY;
        l[mi][0] = 0.0f;      l[mi][1] = 0.0f;
    }
    float o[2][8][4] = {};

    const int wrow_lo = qt * 128 + 32 * w;
    const int ktmax = 2 * qt + 1;

    for (int kt = 0; kt <= ktmax; kt++) {
        // K tile (64x64) -> Ks[kv][d]
        {
            int r = tid >> 4, c = (tid & 15) * 4;
            #pragma unroll
            for (int p = 0; p < 8; p++) {
                int rr = r + 8 * p;
                float4 v = *(const float4*)(kbase + (size_t)(kt * 64 + rr) * QKV_STRIDE + c);
                uint32_t* dst = Ks + rr * FA_PAD + c;
                dst[0] = f32_to_tf32(v.x);
                dst[1] = f32_to_tf32(v.y);
                dst[2] = f32_to_tf32(v.z);
                dst[3] = f32_to_tf32(v.w);
            }
        }
        // V tile transposed -> Vt[d][kv]
        {
            int r = tid >> 4, c = (tid & 15) * 4;
            #pragma unroll
            for (int p = 0; p < 8; p++) {
                int rr = r + 8 * p;
                float4 v = *(const float4*)(vbase + (size_t)(kt * 64 + rr) * QKV_STRIDE + c);
                Vt[(c + 0) * FA_PAD + rr] = f32_to_tf32(v.x);
                Vt[(c + 1) * FA_PAD + rr] = f32_to_tf32(v.y);
                Vt[(c + 2) * FA_PAD + rr] = f32_to_tf32(v.z);
                Vt[(c + 3) * FA_PAD + rr] = f32_to_tf32(v.w);
            }
        }
        __syncthreads();

        const bool active = (kt * 64 <= wrow_lo + 31);
        if (active) {
            // S = Q @ K^T  (32x64 per warp)
            float s[2][8][4] = {};
            const uint32_t* qw = Qs + (32 * w) * FA_PAD;
            #pragma unroll
            for (int kk = 0; kk < 64; kk += 8) {
                uint32_t af[2][4];
                #pragma unroll
                for (int mi = 0; mi < 2; mi++) {
                    const uint32_t* qr = qw + (16 * mi + g) * FA_PAD + kk + tig;
                    af[mi][0] = qr[0];
                    af[mi][1] = qr[8 * FA_PAD];
                    af[mi][2] = qr[4];
                    af[mi][3] = qr[8 * FA_PAD + 4];
                }
                #pragma unroll
                for (int ni = 0; ni < 8; ni++) {
                    const uint32_t* kr = Ks + (8 * ni + g) * FA_PAD + kk + tig;
                    uint32_t b0 = kr[0], b1 = kr[4];
                    #pragma unroll
                    for (int mi = 0; mi < 2; mi++)
                        mma_tf32(s[mi][ni], af[mi][0], af[mi][1], af[mi][2], af[mi][3],
                                 b0, b1);
                }
            }

            // causal mask (tiles overlapping the diagonal)
            if (kt * 64 + 63 > wrow_lo) {
                #pragma unroll
                for (int mi = 0; mi < 2; mi++) {
                    int row0 = wrow_lo + 16 * mi + g;
                    int row1 = row0 + 8;
                    #pragma unroll
                    for (int ni = 0; ni < 8; ni++) {
                        int col = kt * 64 + 8 * ni + 2 * tig;
                        if (col     > row0) s[mi][ni][0] = -INFINITY;
                        if (col + 1 > row0) s[mi][ni][1] = -INFINITY;
                        if (col     > row1) s[mi][ni][2] = -INFINITY;
                        if (col + 1 > row1) s[mi][ni][3] = -INFINITY;
                    }
                }
            }

            // online softmax per mi
            #pragma unroll
            for (int mi = 0; mi < 2; mi++) {
                float mx0 = s[mi][0][0], mx1 = s[mi][0][2];
                #pragma unroll
                for (int ni = 0; ni < 8; ni++) {
                    mx0 = fmaxf(mx0, fmaxf(s[mi][ni][0], s[mi][ni][1]));
                    mx1 = fmaxf(mx1, fmaxf(s[mi][ni][2], s[mi][ni][3]));
                }
                mx0 = fmaxf(mx0, __shfl_xor_sync(0xffffffffu, mx0, 1));
                mx0 = fmaxf(mx0, __shfl_xor_sync(0xffffffffu, mx0, 2));
                mx1 = fmaxf(mx1, __shfl_xor_sync(0xffffffffu, mx1, 1));
                mx1 = fmaxf(mx1, __shfl_xor_sync(0xffffffffu, mx1, 2));

                float mn0 = fmaxf(m[mi][0], mx0), mn1 = fmaxf(m[mi][1], mx1);
                float al0 = __expf(m[mi][0] - mn0), al1 = __expf(m[mi][1] - mn1);

                uint32_t* pw0 = Ps + (32 * w + 16 * mi + g) * FA_PAD + 2 * tig;
                uint32_t* pw1 = pw0 + 8 * FA_PAD;
                float r0 = 0.0f, r1 = 0.0f;
                #pragma unroll
                for (int ni = 0; ni < 8; ni++) {
                    float p0 = __expf(s[mi][ni][0] - mn0);
                    float p1 = __expf(s[mi][ni][1] - mn0);
                    float p2 = __expf(s[mi][ni][2] - mn1);
                    float p3 = __expf(s[mi][ni][3] - mn1);
                    r0 += p0 + p1;
                    r1 += p2 + p3;
                    pw0[8 * ni]     = f32_to_tf32(p0);
                    pw0[8 * ni + 1] = f32_to_tf32(p1);
                    pw1[8 * ni]     = f32_to_tf32(p2);
                    pw1[8 * ni + 1] = f32_to_tf32(p3);
                }
                r0 += __shfl_xor_sync(0xffffffffu, r0, 1);
                r0 += __shfl_xor_sync(0xffffffffu, r0, 2);
                r1 += __shfl_xor_sync(0xffffffffu, r1, 1);
                r1 += __shfl_xor_sync(0xffffffffu, r1, 2);

                l[mi][0] = l[mi][0] * al0 + r0;
                l[mi][1] = l[mi][1] * al1 + r1;
                m[mi][0] = mn0;
                m[mi][1] = mn1;

                #pragma unroll
                for (int ni = 0; ni < 8; ni++) {
                    o[mi][ni][0] *= al0; o[mi][ni][1] *= al0;
                    o[mi][ni][2] *= al1; o[mi][ni][3] *= al1;
                }
            }

            __syncwarp();

            // O += P @ V
            const uint32_t* psw = Ps + (32 * w) * FA_PAD;
            #pragma unroll
            for (int kk = 0; kk < 64; kk += 8) {
                uint32_t af[2][4];
                #pragma unroll
                for (int mi = 0; mi < 2; mi++) {
                    const uint32_t* pr = psw + (16 * mi + g) * FA_PAD + kk + tig;
                    af[mi][0] = pr[0];
                    af[mi][1] = pr[8 * FA_PAD];
                    af[mi][2] = pr[4];
                    af[mi][3] = pr[8 * FA_PAD + 4];
                }
                #pragma unroll
                for (int ni = 0; ni < 8; ni++) {
                    const uint32_t* vr = Vt + (8 * ni + g) * FA_PAD + kk + tig;
                    uint32_t b0 = vr[0], b1 = vr[4];
                    #pragma unroll
                    for (int mi = 0; mi < 2; mi++)
                        mma_tf32(o[mi][ni], af[mi][0], af[mi][1], af[mi][2], af[mi][3],
                                 b0, b1);
                }
            }
        }
        __syncthreads();
    }

    // epilogue
    #pragma unroll
    for (int mi = 0; mi < 2; mi++) {
        float inv0 = 1.0f / l[mi][0], inv1 = 1.0f / l[mi][1];
        int row0 = qt * 128 + 32 * w + 16 * mi + g;
        int row1 = row0 + 8;
        #pragma unroll
        for (int ni = 0; ni < 8; ni++) {
            int col = h * HD + 8 * ni + 2 * tig;
            float2 o0 = {o[mi][ni][0] * inv0, o[mi][ni][1] * inv0};
            float2 o1 = {o[mi][ni][2] * inv1, o[mi][ni][3] * inv1};
            *(float2*)(y + ((size_t)b * T_SZ + row0) * C_SZ + col) = o0;
            *(float2*)(y + ((size_t)b * T_SZ + row1) * C_SZ + col) = o1;
        }
    }
}

// ---------------------------------------------------------------------------
// Launch
// ---------------------------------------------------------------------------
extern "C" void kernel_launch(void* const* d_in, const int* in_sizes, int n_in,
                              void* d_out, int out_size)
{
    const float* x      = (const float*)d_in[0];
    const float* w_attn = (const float*)d_in[1];
    const float* b_attn = (const float*)d_in[2];
    const float* w_proj = (const float*)d_in[3];
    const float* b_proj = (const float*)d_in[4];
    float* out = (float*)d_out;

    float *qkv = nullptr, *y = nullptr;
    cudaGetSymbolAddress((void**)&qkv, g_qkv);
    cudaGetSymbolAddress((void**)&y, g_y);

    cudaFuncSetAttribute(gemm_tf32_kernel,
                         cudaFuncAttributeMaxDynamicSharedMemorySize,
                         G_SMEM_BYTES);
    cudaFuncSetAttribute(flash_tf32_kernel,
                         cudaFuncAttributeMaxDynamicSharedMemorySize,
                         FA_SMEM_BYTES);

    // 1) qkv = x @ w_attn + b_attn
    {
        dim3 grid(3 * C_SZ / 128, MTOK / 128);
        gemm_tf32_kernel<<<grid, 128, G_SMEM_BYTES>>>(x, w_attn, b_attn, qkv,
                                                      MTOK, 3 * C_SZ, C_SZ);
    }
    // 2) RoPE
    {
        int total = MTOK * NH * 32;
        rope_kernel<<<total / 256, 256>>>(qkv);
    }
    // 3) flash attention
    {
        dim3 grid(T_SZ / 128, NH, B_SZ);
        flash_tf32_kernel<<<grid, 128, FA_SMEM_BYTES>>>(qkv, y);
    }
    // 4) out = y @ w_proj + b_proj
    {
        dim3 grid(C_SZ / 128, MTOK / 128);
        gemm_tf32_kernel<<<grid, 128, G_SMEM_BYTES>>>(y, w_proj, b_proj, out,
                                                      MTOK, C_SZ, C_SZ);
    }
}

// round 5
// speedup vs baseline: 3.4947x; 1.0117x over previous
#include <cuda_runtime.h>
#include <math.h>
#include <stdint.h>

// Problem constants
#define B_SZ 4
#define T_SZ 2048
#define C_SZ 1024
#define NH   16
#define HD   64
#define MTOK (B_SZ * T_SZ)
#define QKV_STRIDE (3 * C_SZ)

__device__ float g_qkv[(size_t)MTOK * QKV_STRIDE];  // 96 MB
__device__ float g_y[(size_t)MTOK * C_SZ];          // 32 MB

__device__ __forceinline__ uint32_t f32_to_tf32(float x) {
    uint32_t u;
    asm("cvt.rna.tf32.f32 %0, %1;" : "=r"(u) : "f"(x));
    return u;
}

__device__ __forceinline__ void mma_tf32(float c[4],
    uint32_t a0, uint32_t a1, uint32_t a2, uint32_t a3,
    uint32_t b0, uint32_t b1)
{
    asm volatile(
        "mma.sync.aligned.m16n8k8.row.col.f32.tf32.tf32.f32 "
        "{%0,%1,%2,%3}, {%4,%5,%6,%7}, {%8,%9}, {%0,%1,%2,%3};"
        : "+f"(c[0]), "+f"(c[1]), "+f"(c[2]), "+f"(c[3])
        : "r"(a0), "r"(a1), "r"(a2), "r"(a3), "r"(b0), "r"(b1));
}

// ldmatrix x4: 4 8x8 "b16" matrices; for tf32 each lane gets 1 u32 per matrix.
__device__ __forceinline__ void ldsm4(uint32_t r[4], uint32_t saddr) {
    asm volatile("ldmatrix.sync.aligned.m8n8.x4.shared.b16 {%0,%1,%2,%3}, [%4];"
                 : "=r"(r[0]), "=r"(r[1]), "=r"(r[2]), "=r"(r[3]) : "r"(saddr));
}

__device__ __forceinline__ void cp16(void* smem, const void* g) {
    uint32_t s = (uint32_t)__cvta_generic_to_shared(smem);
    asm volatile("cp.async.cg.shared.global [%0], [%1], 16;" :: "r"(s), "l"(g));
}
#define CP_COMMIT() asm volatile("cp.async.commit_group;")

// ---------------------------------------------------------------------------
// TF32 GEMM, 128x128 tile, K-tile 32, 128 threads = 4 warps, warp tile 64x64.
// cp.async double-buffered; A-fragments via ldmatrix + post-LDS cvt.rna;
// B-fragments scalar LDS + cvt (K-major layout can't feed LDSM).
// ---------------------------------------------------------------------------
#define G_AS_PAD 36
#define G_BS_PAD 136
#define G_STAGE (128 * G_AS_PAD + 32 * G_BS_PAD)   // 8960 u32
#define G_SMEM_BYTES (2 * G_STAGE * 4)             // 71680

__global__ __launch_bounds__(128) void gemm_tf32_kernel(
    const float* __restrict__ A, const float* __restrict__ Bm,
    const float* __restrict__ bias, float* __restrict__ C,
    int M, int N, int K)
{
    extern __shared__ float gsm[];
    const uint32_t gsm_sh = (uint32_t)__cvta_generic_to_shared(gsm);

    const int tid  = threadIdx.x;
    const int wid  = tid >> 5;
    const int lane = tid & 31;
    const int g    = lane >> 2;
    const int tig  = lane & 3;
    const int wm   = (wid & 1) * 64;
    const int wn   = (wid >> 1) * 64;

    const int bm = blockIdx.y * 128;
    const int bn = blockIdx.x * 128;

    // LDSM lane address offsets (A-type: 16x8 fragment)
    const int arow = (lane & 7) + ((lane >> 3) & 1) * 8;
    const int acol = (lane >> 4) * 4;
    const uint32_t a_frag_base = gsm_sh + 4u * ((wm + arow) * G_AS_PAD + acol);

    // copy coords
    const int a_r = tid >> 3;
    const int a_c = (tid & 7) * 4;
    const int b_r = tid >> 5;
    const int b_c = lane * 4;

    float acc[4][8][4] = {};

    // prologue: stage 0
    {
        float* As_ = gsm;
        float* Bs_ = gsm + 128 * G_AS_PAD;
        #pragma unroll
        for (int p = 0; p < 8; p++) {
            cp16(&As_[(a_r + 16 * p) * G_AS_PAD + a_c],
                 A + (size_t)(bm + a_r + 16 * p) * K + a_c);
            cp16(&Bs_[(b_r + 4 * p) * G_BS_PAD + b_c],
                 Bm + (size_t)(b_r + 4 * p) * N + bn + b_c);
        }
        CP_COMMIT();
    }

    const int NT = K >> 5;
    for (int kt = 0; kt < NT; kt++) {
        if (kt + 1 < NT) {
            float* As_ = gsm + ((kt + 1) & 1) * G_STAGE;
            float* Bs_ = As_ + 128 * G_AS_PAD;
            const int k0 = (kt + 1) * 32;
            #pragma unroll
            for (int p = 0; p < 8; p++) {
                cp16(&As_[(a_r + 16 * p) * G_AS_PAD + a_c],
                     A + (size_t)(bm + a_r + 16 * p) * K + k0 + a_c);
                cp16(&Bs_[(b_r + 4 * p) * G_BS_PAD + b_c],
                     Bm + (size_t)(k0 + b_r + 4 * p) * N + bn + b_c);
            }
            CP_COMMIT();
            asm volatile("cp.async.wait_group 1;");
        } else {
            asm volatile("cp.async.wait_group 0;");
        }
        __syncthreads();

        const uint32_t a_base_kt = a_frag_base + 4u * ((kt & 1) * G_STAGE);
        const float* Bs_ = gsm + (kt & 1) * G_STAGE + 128 * G_AS_PAD;

        #pragma unroll
        for (int kk = 0; kk < 32; kk += 8) {
            uint32_t af[4][4];
            #pragma unroll
            for (int mi = 0; mi < 4; mi++) {
                uint32_t raw[4];
                ldsm4(raw, a_base_kt + 4u * (16 * mi * G_AS_PAD + kk));
                af[mi][0] = f32_to_tf32(__uint_as_float(raw[0]));
                af[mi][1] = f32_to_tf32(__uint_as_float(raw[1]));
                af[mi][2] = f32_to_tf32(__uint_as_float(raw[2]));
                af[mi][3] = f32_to_tf32(__uint_as_float(raw[3]));
            }
            #pragma unroll
            for (int ni = 0; ni < 8; ni++) {
                int cn = wn + 8 * ni + g;
                uint32_t b0 = f32_to_tf32(Bs_[(kk + tig) * G_BS_PAD + cn]);
                uint32_t b1 = f32_to_tf32(Bs_[(kk + tig + 4) * G_BS_PAD + cn]);
                #pragma unroll
                for (int mi = 0; mi < 4; mi++)
                    mma_tf32(acc[mi][ni], af[mi][0], af[mi][1], af[mi][2], af[mi][3],
                             b0, b1);
            }
        }
        __syncthreads();
    }

    // epilogue
    #pragma unroll
    for (int ni = 0; ni < 8; ni++) {
        int col = bn + wn + 8 * ni + 2 * tig;
        float bx = bias[col], by = bias[col + 1];
        #pragma unroll
        for (int mi = 0; mi < 4; mi++) {
            int row0 = bm + wm + 16 * mi + g;
            float2 o0 = {acc[mi][ni][0] + bx, acc[mi][ni][1] + by};
            float2 o1 = {acc[mi][ni][2] + bx, acc[mi][ni][3] + by};
            *(float2*)(C + (size_t)row0 * N + col) = o0;
            *(float2*)(C + (size_t)(row0 + 8) * N + col) = o1;
        }
    }
}

// ---------------------------------------------------------------------------
// RoPE (unchanged)
// ---------------------------------------------------------------------------
__global__ __launch_bounds__(256) void rope_kernel(float* __restrict__ qkv)
{
    int idx = blockIdx.x * blockDim.x + threadIdx.x;
    int pair = idx & 31;
    int h    = (idx >> 5) & (NH - 1);
    int tok  = idx >> 9;
    int t    = tok & (T_SZ - 1);

    float invf = powf(10000.0f, -(float)pair / 32.0f);
    float ang = (float)t * invf;
    float s, c;
    sincosf(ang, &s, &c);

    size_t base = (size_t)tok * QKV_STRIDE + h * HD;
    float* q = qkv + base;
    float* k = qkv + base + C_SZ;

    float q1 = q[pair], q2 = q[pair + 32];
    q[pair]      = q1 * c - q2 * s;
    q[pair + 32] = q2 * c + q1 * s;
    float k1 = k[pair], k2 = k[pair + 32];
    k[pair]      = k1 * c - k2 * s;
    k[pair + 32] = k2 * c + k1 * s;
}

// ---------------------------------------------------------------------------
// TF32 flash attention (causal). BM=128, 128 threads = 4 warps, warp tile
// 32 q-rows x 64 kv. All fragment loads via ldmatrix.
// ---------------------------------------------------------------------------
#define FA_PAD 68
#define FQ 0
#define FK (128 * FA_PAD)
#define FV (FK + 64 * FA_PAD)
#define FP (FV + 64 * FA_PAD)
#define FA_SMEM_U32 (FP + 128 * FA_PAD)
#define FA_SMEM_BYTES (FA_SMEM_U32 * 4)

__global__ __launch_bounds__(128) void flash_tf32_kernel(
    const float* __restrict__ qkv, float* __restrict__ y)
{
    extern __shared__ uint32_t fsm[];
    uint32_t* Qs = fsm + FQ;
    uint32_t* Ks = fsm + FK;
    uint32_t* Vt = fsm + FV;
    uint32_t* Ps = fsm + FP;
    const uint32_t fsm_sh = (uint32_t)__cvta_generic_to_shared(fsm);

    const int qt = blockIdx.x;
    const int h  = blockIdx.y;
    const int b  = blockIdx.z;
    const int tid  = threadIdx.x;
    const int w    = tid >> 5;
    const int lane = tid & 31;
    const int g    = lane >> 2;
    const int tig  = lane & 3;

    // LDSM lane offsets: A-type (16x8 frag), B-type (two 8x8 n-frags)
    const int arow = (lane & 7) + ((lane >> 3) & 1) * 8;
    const int acol = (lane >> 4) * 4;
    const int brow = (lane & 7) + (lane >> 4) * 8;
    const int bcol = ((lane >> 3) & 1) * 4;

    const uint32_t aq_base = fsm_sh + 4u * (FQ + (32 * w + arow) * FA_PAD + acol);
    const uint32_t ap_base = fsm_sh + 4u * (FP + (32 * w + arow) * FA_PAD + acol);
    const uint32_t bk_base = fsm_sh + 4u * (FK + brow * FA_PAD + bcol);
    const uint32_t bv_base = fsm_sh + 4u * (FV + brow * FA_PAD + bcol);

    const float* qbase = qkv + (size_t)b * T_SZ * QKV_STRIDE + h * HD;
    const float* kbase = qbase + C_SZ;
    const float* vbase = qbase + 2 * C_SZ;

    // load Q (128x64), scale 1/8, tf32
    {
        int r = tid >> 4, c = (tid & 15) * 4;
        #pragma unroll
        for (int p = 0; p < 16; p++) {
            int rr = r + 8 * p;
            float4 v = *(const float4*)(qbase + (size_t)(qt * 128 + rr) * QKV_STRIDE + c);
            uint32_t* dst = Qs + rr * FA_PAD + c;
            dst[0] = f32_to_tf32(v.x * 0.125f);
            dst[1] = f32_to_tf32(v.y * 0.125f);
            dst[2] = f32_to_tf32(v.z * 0.125f);
            dst[3] = f32_to_tf32(v.w * 0.125f);
        }
    }

    float m[2][2], l[2][2];
    #pragma unroll
    for (int mi = 0; mi < 2; mi++) {
        m[mi][0] = -INFINITY; m[mi][1] = -INFINITY;
        l[mi][0] = 0.0f;      l[mi][1] = 0.0f;
    }
    float o[2][8][4] = {};

    const int wrow_lo = qt * 128 + 32 * w;
    const int ktmax = 2 * qt + 1;

    for (int kt = 0; kt <= ktmax; kt++) {
        // K tile (64x64) -> Ks[kv][d]
        {
            int r = tid >> 4, c = (tid & 15) * 4;
            #pragma unroll
            for (int p = 0; p < 8; p++) {
                int rr = r + 8 * p;
                float4 v = *(const float4*)(kbase + (size_t)(kt * 64 + rr) * QKV_STRIDE + c);
                uint32_t* dst = Ks + rr * FA_PAD + c;
                dst[0] = f32_to_tf32(v.x);
                dst[1] = f32_to_tf32(v.y);
                dst[2] = f32_to_tf32(v.z);
                dst[3] = f32_to_tf32(v.w);
            }
        }
        // V tile transposed -> Vt[d][kv]
        {
            int r = tid >> 4, c = (tid & 15) * 4;
            #pragma unroll
            for (int p = 0; p < 8; p++) {
                int rr = r + 8 * p;
                float4 v = *(const float4*)(vbase + (size_t)(kt * 64 + rr) * QKV_STRIDE + c);
                Vt[(c + 0) * FA_PAD + rr] = f32_to_tf32(v.x);
                Vt[(c + 1) * FA_PAD + rr] = f32_to_tf32(v.y);
                Vt[(c + 2) * FA_PAD + rr] = f32_to_tf32(v.z);
                Vt[(c + 3) * FA_PAD + rr] = f32_to_tf32(v.w);
            }
        }
        __syncthreads();

        const bool active = (kt * 64 <= wrow_lo + 31);
        if (active) {
            // S = Q @ K^T  (32x64 per warp)
            float s[2][8][4] = {};
            #pragma unroll
            for (int kk = 0; kk < 64; kk += 8) {
                uint32_t af[2][4];
                ldsm4(af[0], aq_base + 4u * kk);
                ldsm4(af[1], aq_base + 4u * (16 * FA_PAD + kk));
                #pragma unroll
                for (int p = 0; p < 4; p++) {
                    uint32_t bq[4];
                    ldsm4(bq, bk_base + 4u * (16 * p * FA_PAD + kk));
                    #pragma unroll
                    for (int mi = 0; mi < 2; mi++) {
                        mma_tf32(s[mi][2 * p],     af[mi][0], af[mi][1], af[mi][2], af[mi][3], bq[0], bq[1]);
                        mma_tf32(s[mi][2 * p + 1], af[mi][0], af[mi][1], af[mi][2], af[mi][3], bq[2], bq[3]);
                    }
                }
            }

            // causal mask (tiles overlapping the diagonal)
            if (kt * 64 + 63 > wrow_lo) {
                #pragma unroll
                for (int mi = 0; mi < 2; mi++) {
                    int row0 = wrow_lo + 16 * mi + g;
                    int row1 = row0 + 8;
                    #pragma unroll
                    for (int ni = 0; ni < 8; ni++) {
                        int col = kt * 64 + 8 * ni + 2 * tig;
                        if (col     > row0) s[mi][ni][0] = -INFINITY;
                        if (col + 1 > row0) s[mi][ni][1] = -INFINITY;
                        if (col     > row1) s[mi][ni][2] = -INFINITY;
                        if (col + 1 > row1) s[mi][ni][3] = -INFINITY;
                    }
                }
            }

            // online softmax per mi
            #pragma unroll
            for (int mi = 0; mi < 2; mi++) {
                float mx0 = s[mi][0][0], mx1 = s[mi][0][2];
                #pragma unroll
                for (int ni = 0; ni < 8; ni++) {
                    mx0 = fmaxf(mx0, fmaxf(s[mi][ni][0], s[mi][ni][1]));
                    mx1 = fmaxf(mx1, fmaxf(s[mi][ni][2], s[mi][ni][3]));
                }
                mx0 = fmaxf(mx0, __shfl_xor_sync(0xffffffffu, mx0, 1));
                mx0 = fmaxf(mx0, __shfl_xor_sync(0xffffffffu, mx0, 2));
                mx1 = fmaxf(mx1, __shfl_xor_sync(0xffffffffu, mx1, 1));
                mx1 = fmaxf(mx1, __shfl_xor_sync(0xffffffffu, mx1, 2));

                float mn0 = fmaxf(m[mi][0], mx0), mn1 = fmaxf(m[mi][1], mx1);
                float al0 = __expf(m[mi][0] - mn0), al1 = __expf(m[mi][1] - mn1);

                uint32_t* pw0 = Ps + (32 * w + 16 * mi + g) * FA_PAD + 2 * tig;
                uint32_t* pw1 = pw0 + 8 * FA_PAD;
                float r0 = 0.0f, r1 = 0.0f;
                #pragma unroll
                for (int ni = 0; ni < 8; ni++) {
                    float p0 = __expf(s[mi][ni][0] - mn0);
                    float p1 = __expf(s[mi][ni][1] - mn0);
                    float p2 = __expf(s[mi][ni][2] - mn1);
                    float p3 = __expf(s[mi][ni][3] - mn1);
                    r0 += p0 + p1;
                    r1 += p2 + p3;
                    pw0[8 * ni]     = f32_to_tf32(p0);
                    pw0[8 * ni + 1] = f32_to_tf32(p1);
                    pw1[8 * ni]     = f32_to_tf32(p2);
                    pw1[8 * ni + 1] = f32_to_tf32(p3);
                }
                r0 += __shfl_xor_sync(0xffffffffu, r0, 1);
                r0 += __shfl_xor_sync(0xffffffffu, r0, 2);
                r1 += __shfl_xor_sync(0xffffffffu, r1, 1);
                r1 += __shfl_xor_sync(0xffffffffu, r1, 2);

                l[mi][0] = l[mi][0] * al0 + r0;
                l[mi][1] = l[mi][1] * al1 + r1;
                m[mi][0] = mn0;
                m[mi][1] = mn1;

                #pragma unroll
                for (int ni = 0; ni < 8; ni++) {
                    o[mi][ni][0] *= al0; o[mi][ni][1] *= al0;
                    o[mi][ni][2] *= al1; o[mi][ni][3] *= al1;
                }
            }

            __syncwarp();

            // O += P @ V
            #pragma unroll
            for (int kk = 0; kk < 64; kk += 8) {
                uint32_t af[2][4];
                ldsm4(af[0], ap_base + 4u * kk);
                ldsm4(af[1], ap_base + 4u * (16 * FA_PAD + kk));
                #pragma unroll
                for (int p = 0; p < 4; p++) {
                    uint32_t bq[4];
                    ldsm4(bq, bv_base + 4u * (16 * p * FA_PAD + kk));
                    #pragma unroll
                    for (int mi = 0; mi < 2; mi++) {
                        mma_tf32(o[mi][2 * p],     af[mi][0], af[mi][1], af[mi][2], af[mi][3], bq[0], bq[1]);
                        mma_tf32(o[mi][2 * p + 1], af[mi][0], af[mi][1], af[mi][2], af[mi][3], bq[2], bq[3]);
                    }
                }
            }
        }
        __syncthreads();
    }

    // epilogue
    #pragma unroll
    for (int mi = 0; mi < 2; mi++) {
        float inv0 = 1.0f / l[mi][0], inv1 = 1.0f / l[mi][1];
        int row0 = qt * 128 + 32 * w + 16 * mi + g;
        int row1 = row0 + 8;
        #pragma unroll
        for (int ni = 0; ni < 8; ni++) {
            int col = h * HD + 8 * ni + 2 * tig;
            float2 o0 = {o[mi][ni][0] * inv0, o[mi][ni][1] * inv0};
            float2 o1 = {o[mi][ni][2] * inv1, o[mi][ni][3] * inv1};
            *(float2*)(y + ((size_t)b * T_SZ + row0) * C_SZ + col) = o0;
            *(float2*)(y + ((size_t)b * T_SZ + row1) * C_SZ + col) = o1;
        }
    }
}

// ---------------------------------------------------------------------------
// Launch
// ---------------------------------------------------------------------------
extern "C" void kernel_launch(void* const* d_in, const int* in_sizes, int n_in,
                              void* d_out, int out_size)
{
    const float* x      = (const float*)d_in[0];
    const float* w_attn = (const float*)d_in[1];
    const float* b_attn = (const float*)d_in[2];
    const float* w_proj = (const float*)d_in[3];
    const float* b_proj = (const float*)d_in[4];
    float* out = (float*)d_out;

    float *qkv = nullptr, *y = nullptr;
    cudaGetSymbolAddress((void**)&qkv, g_qkv);
    cudaGetSymbolAddress((void**)&y, g_y);

    cudaFuncSetAttribute(gemm_tf32_kernel,
                         cudaFuncAttributeMaxDynamicSharedMemorySize,
                         G_SMEM_BYTES);
    cudaFuncSetAttribute(flash_tf32_kernel,
                         cudaFuncAttributeMaxDynamicSharedMemorySize,
                         FA_SMEM_BYTES);

    // 1) qkv = x @ w_attn + b_attn
    {
        dim3 grid(3 * C_SZ / 128, MTOK / 128);
        gemm_tf32_kernel<<<grid, 128, G_SMEM_BYTES>>>(x, w_attn, b_attn, qkv,
                                                      MTOK, 3 * C_SZ, C_SZ);
    }
    // 2) RoPE
    {
        int total = MTOK * NH * 32;
        rope_kernel<<<total / 256, 256>>>(qkv);
    }
    // 3) flash attention
    {
        dim3 grid(T_SZ / 128, NH, B_SZ);
        flash_tf32_kernel<<<grid, 128, FA_SMEM_BYTES>>>(qkv, y);
    }
    // 4) out = y @ w_proj + b_proj
    {
        dim3 grid(C_SZ / 128, MTOK / 128);
        gemm_tf32_kernel<<<grid, 128, G_SMEM_BYTES>>>(y, w_proj, b_proj, out,
                                                      MTOK, C_SZ, C_SZ);
    }
}